// round 15
// baseline (speedup 1.0000x reference)
#include <cuda_runtime.h>
#include <cuda_bf16.h>
#include <math.h>
#include <stdint.h>

typedef __nv_bfloat16 bf16;

constexpr int D_MODEL = 1024;
constexpr int SEQ     = 2048;
constexpr int BATCH   = 2;
constexpr int NH      = 16;
constexpr int DK      = 64;
constexpr int DFF     = 4096;
constexpr int ROWS    = BATCH * SEQ;     // 4096
constexpr float EPS   = 1e-5f;
constexpr long long OUT_ELEMS  = (long long)ROWS * D_MODEL;
constexpr long long ATTN_ELEMS = (long long)BATCH * NH * SEQ * SEQ;
constexpr int NROWS_ATTN = BATCH * NH * SEQ;   // 65536

// ---------------- device scratch ----------------
__device__ bf16 g_xhi [ROWS * D_MODEL], g_xlo [ROWS * D_MODEL];
__device__ bf16 g_wqt_hi[D_MODEL * D_MODEL], g_wqt_lo[D_MODEL * D_MODEL];
__device__ bf16 g_wkt_hi[D_MODEL * D_MODEL], g_wkt_lo[D_MODEL * D_MODEL];
__device__ bf16 g_wvt_hi[D_MODEL * D_MODEL], g_wvt_lo[D_MODEL * D_MODEL];
__device__ bf16 g_wot_hi[D_MODEL * D_MODEL], g_wot_lo[D_MODEL * D_MODEL];
__device__ bf16 g_w1t_hi[(long long)D_MODEL * DFF], g_w1t_lo[(long long)D_MODEL * DFF];
__device__ bf16 g_w2t_hi[(long long)D_MODEL * DFF], g_w2t_lo[(long long)D_MODEL * DFF];
__device__ bf16 g_Qhi [ROWS * D_MODEL], g_Qlo [ROWS * D_MODEL];
__device__ bf16 g_Khi [ROWS * D_MODEL], g_Klo [ROWS * D_MODEL];
__device__ bf16 g_Vhi [ROWS * D_MODEL], g_Vlo [ROWS * D_MODEL];
__device__ bf16 g_ctxhi[ROWS * D_MODEL], g_ctxlo[ROWS * D_MODEL];
__device__ bf16 g_hhi [ROWS * D_MODEL], g_hlo [ROWS * D_MODEL];
__device__ bf16 g_ffhi[(long long)ROWS * DFF], g_fflo[(long long)ROWS * DFF];
__device__ float g_T1[ROWS * D_MODEL];
__device__ float g_H [ROWS * D_MODEL];
__device__ float g_rowsum[NROWS_ATTN];
__device__ float g_attn_fallback[ATTN_ELEMS];

// ---------------- PTX helpers ----------------
__device__ __forceinline__ uint32_t smem_u32(const void* p) {
    uint32_t a;
    asm("{ .reg .u64 t; cvta.to.shared.u64 t, %1; cvt.u32.u64 %0, t; }" : "=r"(a) : "l"(p));
    return a;
}
#define CP16(d, s)   asm volatile("cp.async.cg.shared.global [%0], [%1], 16;" :: "r"(d), "l"(s))
#define CP_COMMIT()  asm volatile("cp.async.commit_group;" ::: "memory")
#define CP_WAIT0()   asm volatile("cp.async.wait_group 0;" ::: "memory")
#define CP_WAIT1()   asm volatile("cp.async.wait_group 1;" ::: "memory")

#define LDSM4(r0, r1, r2, r3, a) \
    asm volatile("ldmatrix.sync.aligned.m8n8.x4.shared.b16 {%0,%1,%2,%3}, [%4];" \
                 : "=r"(r0), "=r"(r1), "=r"(r2), "=r"(r3) : "r"(a))
#define LDSM4T(r0, r1, r2, r3, a) \
    asm volatile("ldmatrix.sync.aligned.m8n8.x4.trans.shared.b16 {%0,%1,%2,%3}, [%4];" \
                 : "=r"(r0), "=r"(r1), "=r"(r2), "=r"(r3) : "r"(a))

__device__ __forceinline__ void mma_bf16(float* c, const uint32_t* a, uint32_t b0, uint32_t b1) {
    asm volatile(
        "mma.sync.aligned.m16n8k16.row.col.f32.bf16.bf16.f32 "
        "{%0,%1,%2,%3}, {%4,%5,%6,%7}, {%8,%9}, {%0,%1,%2,%3};"
        : "+f"(c[0]), "+f"(c[1]), "+f"(c[2]), "+f"(c[3])
        : "r"(a[0]), "r"(a[1]), "r"(a[2]), "r"(a[3]), "r"(b0), "r"(b1));
}

__device__ __forceinline__ void split2(float v, bf16& h, bf16& l) {
    h = __float2bfloat16(v);
    l = __float2bfloat16(v - __bfloat162float(h));
}

// ---------------------------------------------------------------------------
// Split-bf16 GEMM via mma.sync.  128x128 CTA tile, 128 threads (4 warps in a
// 2x2 grid), 64x64 warp tile — doubles B-fragment reuse vs the 64x32 version
// (smem intensity 16 -> 24 MAC/B).  RS compile-time as in R13.
// ---------------------------------------------------------------------------
template<int BN, bool RS>
__device__ __forceinline__ void mma_gemm(
    const bf16* __restrict__ Ah, const bf16* __restrict__ Al, int lda,
    const bf16* __restrict__ Bh, const bf16* __restrict__ Bl, int ldb,
    int K, int m0, int n0,
    const float* __restrict__ bias, float scale, int act,
    float* __restrict__ Cf, int ldcf,
    bf16* __restrict__ Chi, bf16* __restrict__ Clo, int ldc2,
    float* __restrict__ rowsum)
{
    static_assert(BN == 128, "BN must be 128");
    constexpr int ASZ   = 128 * 80;
    constexpr int BSZ   = BN * 80;
    constexpr int STAGE = 2 * ASZ + 2 * BSZ;      // 40960
    constexpr int WN_W  = 2;                      // warps along n (64 cols each)
    constexpr int M_IT  = 4;                      // 4 x m16 = 64 rows per warp

    extern __shared__ char sm[];
    const uint32_t sb = smem_u32(sm);

    const int t = threadIdx.x, lane = t & 31, w = t >> 5;   // 128 threads
    const int wm = w >> 1, wn = w & 1;                      // 2x2 warp grid

    float acc[M_IT][8][4];
    #pragma unroll
    for (int i = 0; i < M_IT; i++)
        #pragma unroll
        for (int j = 0; j < 8; j++)
            #pragma unroll
            for (int q = 0; q < 4; q++) acc[i][j][q] = 0.0f;

    const int NCH = K / 32;

    auto issue = [&](int ch, int buf) {
        uint32_t s0 = sb + buf * STAGE;
        int k0 = ch * 32;
        #pragma unroll
        for (int i = 0; i < 4; i++) {                       // A: 128 rows x 64B
            int c = i * 128 + t;
            int r = c >> 2, cb = (c & 3) << 4;
            const char* gh = (const char*)(Ah + (size_t)(m0 + r) * lda + k0) + cb;
            const char* gl = (const char*)(Al + (size_t)(m0 + r) * lda + k0) + cb;
            CP16(s0 + r * 80 + cb, gh);
            CP16(s0 + ASZ + r * 80 + cb, gl);
        }
        #pragma unroll
        for (int i = 0; i < 4; i++) {                       // B: 128 rows x 64B
            int c = i * 128 + t;
            int r = c >> 2, cb = (c & 3) << 4;
            const char* gh = (const char*)(Bh + (size_t)(n0 + r) * ldb + k0) + cb;
            const char* gl = (const char*)(Bl + (size_t)(n0 + r) * ldb + k0) + cb;
            CP16(s0 + 2 * ASZ + r * 80 + cb, gh);
            CP16(s0 + 2 * ASZ + BSZ + r * 80 + cb, gl);
        }
    };

    auto compute = [&](int buf) {
        uint32_t aAh = sb + buf * STAGE;
        uint32_t aAl = aAh + ASZ;
        uint32_t aBh = aAl + ASZ;
        uint32_t aBl = aBh + BSZ;

        #pragma unroll
        for (int ks = 0; ks < 2; ks++) {
            uint32_t bh[16], bl[16];
            #pragma unroll
            for (int p = 0; p < 4; p++) {                   // 64 cols of B
                int nb = wn * 64 + p * 16;
                uint32_t ad = (uint32_t)((nb + ((lane >> 4) << 3) + (lane & 7)) * 80 +
                                         ks * 32 + ((lane >> 3) & 1) * 16);
                LDSM4(bh[4*p], bh[4*p+1], bh[4*p+2], bh[4*p+3], aBh + ad);
                LDSM4(bl[4*p], bl[4*p+1], bl[4*p+2], bl[4*p+3], aBl + ad);
            }
            uint32_t af[M_IT][4], au[M_IT];
            #pragma unroll
            for (int mi = 0; mi < M_IT; mi++) {
                au[mi] = (uint32_t)((wm * 64 + mi * 16 + (lane & 15)) * 80 +
                                    ks * 32 + (lane >> 4) * 16);
                LDSM4(af[mi][0], af[mi][1], af[mi][2], af[mi][3], aAh + au[mi]);
            }
            #pragma unroll
            for (int mi = 0; mi < M_IT; mi++)
                #pragma unroll
                for (int ni = 0; ni < 8; ni++) {
                    int bi = (ni >> 1) * 4 + (ni & 1) * 2;
                    mma_bf16(acc[mi][ni], af[mi], bh[bi], bh[bi + 1]);
                }
            #pragma unroll
            for (int mi = 0; mi < M_IT; mi++)
                #pragma unroll
                for (int ni = 0; ni < 8; ni++) {
                    int bi = (ni >> 1) * 4 + (ni & 1) * 2;
                    mma_bf16(acc[mi][ni], af[mi], bl[bi], bl[bi + 1]);
                }
            #pragma unroll
            for (int mi = 0; mi < M_IT; mi++)
                LDSM4(af[mi][0], af[mi][1], af[mi][2], af[mi][3], aAl + au[mi]);
            #pragma unroll
            for (int mi = 0; mi < M_IT; mi++)
                #pragma unroll
                for (int ni = 0; ni < 8; ni++) {
                    int bi = (ni >> 1) * 4 + (ni & 1) * 2;
                    mma_bf16(acc[mi][ni], af[mi], bh[bi], bh[bi + 1]);
                }
        }
    };

    issue(0, 0);
    CP_COMMIT();
    for (int ch = 0; ch < NCH; ch++) {
        int buf = ch & 1;
        if (ch + 1 < NCH) { issue(ch + 1, buf ^ 1); CP_COMMIT(); CP_WAIT1(); }
        else              { CP_WAIT0(); }
        __syncthreads();
        compute(buf);
        __syncthreads();
    }

    const int g = lane >> 2, tq = lane & 3;
    float* sRed = reinterpret_cast<float*>(sm);     // reuse pipeline smem (RS only)
    #pragma unroll
    for (int mi = 0; mi < M_IT; mi++) {
        int mA = m0 + wm * 64 + mi * 16 + g;
        float srow0 = 0.0f, srow1 = 0.0f;
        #pragma unroll
        for (int ni = 0; ni < 8; ni++) {
            int n = n0 + wn * 64 + ni * 8 + 2 * tq;
            float b0v = 0.f, b1v = 0.f;
            if (bias) { b0v = bias[n]; b1v = bias[n + 1]; }
            float* c = acc[mi][ni];
            float v00 = c[0] * scale + b0v, v01 = c[1] * scale + b1v;
            float v10 = c[2] * scale + b0v, v11 = c[3] * scale + b1v;
            if (act) {
                v00 = v00 * normcdff(v00); v01 = v01 * normcdff(v01);
                v10 = v10 * normcdff(v10); v11 = v11 * normcdff(v11);
            }
            if (RS) {
                v00 = __expf(v00); v01 = __expf(v01);
                v10 = __expf(v10); v11 = __expf(v11);
                srow0 += v00 + v01; srow1 += v10 + v11;
            }
            if (Cf) {
                *reinterpret_cast<float2*>(&Cf[(size_t)mA * ldcf + n])       = make_float2(v00, v01);
                *reinterpret_cast<float2*>(&Cf[(size_t)(mA + 8) * ldcf + n]) = make_float2(v10, v11);
            }
            if (Chi) {
                bf16 h0, l0, h1, l1;
                split2(v00, h0, l0); split2(v01, h1, l1);
                *reinterpret_cast<__nv_bfloat162*>(&Chi[(size_t)mA * ldc2 + n]) = __halves2bfloat162(h0, h1);
                *reinterpret_cast<__nv_bfloat162*>(&Clo[(size_t)mA * ldc2 + n]) = __halves2bfloat162(l0, l1);
                split2(v10, h0, l0); split2(v11, h1, l1);
                *reinterpret_cast<__nv_bfloat162*>(&Chi[(size_t)(mA + 8) * ldc2 + n]) = __halves2bfloat162(h0, h1);
                *reinterpret_cast<__nv_bfloat162*>(&Clo[(size_t)(mA + 8) * ldc2 + n]) = __halves2bfloat162(l0, l1);
            }
        }
        if (RS) {
            #pragma unroll
            for (int s = 1; s <= 2; s <<= 1) {
                srow0 += __shfl_xor_sync(~0u, srow0, s);
                srow1 += __shfl_xor_sync(~0u, srow1, s);
            }
            if (tq == 0) {
                int r0 = wm * 64 + mi * 16 + g;
                sRed[r0 * WN_W + wn] = srow0;
                sRed[(r0 + 8) * WN_W + wn] = srow1;
            }
        }
    }
    if (RS) {
        __syncthreads();
        if (t < 128) {
            float s = sRed[t * WN_W] + sRed[t * WN_W + 1];
            atomicAdd(&rowsum[m0 + t], s);
        }
    }
}

// ---------------- GEMM wrapper kernels (128 threads, 2 CTAs/SM) ----------------
__global__ void __launch_bounds__(128, 2)
k_qkv(const float* bq, const float* bk, const float* bv)
{
    int z = blockIdx.z;
    const bf16 *Bh, *Bl; const float* bias; bf16 *Chi, *Clo;
    if (z == 0)      { Bh = g_wqt_hi; Bl = g_wqt_lo; bias = bq; Chi = g_Qhi; Clo = g_Qlo; }
    else if (z == 1) { Bh = g_wkt_hi; Bl = g_wkt_lo; bias = bk; Chi = g_Khi; Clo = g_Klo; }
    else             { Bh = g_wvt_hi; Bl = g_wvt_lo; bias = bv; Chi = g_Vhi; Clo = g_Vlo; }
    mma_gemm<128, false>(g_xhi, g_xlo, D_MODEL, Bh, Bl, D_MODEL, D_MODEL,
                         blockIdx.y * 128, blockIdx.x * 128,
                         bias, 1.0f, 0, nullptr, 0, Chi, Clo, D_MODEL, nullptr);
}

// scores: writes u = exp(QK^T/8) and row sums (softmax-free path)
__global__ void __launch_bounds__(128, 2)
k_scores(float* attn)
{
    int z = blockIdx.z, b = z >> 4, h = z & 15;
    size_t off = (size_t)b * SEQ * D_MODEL + (size_t)h * DK;
    mma_gemm<128, true>(g_Qhi + off, g_Qlo + off, D_MODEL,
                        g_Khi + off, g_Klo + off, D_MODEL, DK,
                        blockIdx.y * 128, blockIdx.x * 128,
                        nullptr, 0.125f, 0,
                        attn + (size_t)z * SEQ * SEQ, SEQ, nullptr, nullptr, 0,
                        g_rowsum + (size_t)z * SEQ);
}

__global__ void __launch_bounds__(128, 2)
k_wo(const float* bo)
{
    mma_gemm<128, false>(g_ctxhi, g_ctxlo, D_MODEL, g_wot_hi, g_wot_lo, D_MODEL, D_MODEL,
                         blockIdx.y * 128, blockIdx.x * 128,
                         bo, 1.0f, 0, g_T1, D_MODEL, nullptr, nullptr, 0, nullptr);
}

__global__ void __launch_bounds__(128, 2)
k_ff1(const float* bf1)
{
    mma_gemm<128, false>(g_hhi, g_hlo, D_MODEL, g_w1t_hi, g_w1t_lo, D_MODEL, D_MODEL,
                         blockIdx.y * 128, blockIdx.x * 128,
                         bf1, 1.0f, 1, nullptr, 0, g_ffhi, g_fflo, DFF, nullptr);
}

__global__ void __launch_bounds__(128, 2)
k_ff2(const float* bf2)
{
    mma_gemm<128, false>(g_ffhi, g_fflo, DFF, g_w2t_hi, g_w2t_lo, DFF, DFF,
                         blockIdx.y * 128, blockIdx.x * 128,
                         bf2, 1.0f, 0, g_T1, D_MODEL, nullptr, nullptr, 0, nullptr);
}

// ---------------------------------------------------------------------------
// ctx = softmax(attn) @ V.  (Proven R13 kernel, unchanged: 256 threads.)
// ---------------------------------------------------------------------------
constexpr int CTX_F   = 18432;
constexpr int CTX_AB  = 10240;
constexpr int CTX_V   = 4608;
constexpr int CO_F    = 0;
constexpr int CO_AH   = 2 * CTX_F;
constexpr int CO_AL   = CO_AH + CTX_AB;
constexpr int CO_V    = CO_AL + CTX_AB;
constexpr int CO_LI   = CO_V + 4 * CTX_V;
constexpr int CTX_SM  = CO_LI + 512;

__global__ void __launch_bounds__(256)
k_ctx(float* __restrict__ attn_base)
{
    const int z = blockIdx.z, b = z >> 4, h = z & 15;
    const int m0 = blockIdx.y * 128;
    float* A = attn_base + (size_t)z * SEQ * SEQ + (size_t)m0 * SEQ;
    const size_t vb = (size_t)b * SEQ * D_MODEL + (size_t)h * DK;
    const bf16* Vh = g_Vhi + vb;
    const bf16* Vl = g_Vlo + vb;

    extern __shared__ char sm[];
    const uint32_t sb = smem_u32(sm);
    float* sLinv = reinterpret_cast<float*>(sm + CO_LI);

    const int t = threadIdx.x, lane = t & 31, w = t >> 5;
    const int wm = w >> 1, wn = w & 1;
    const int g = lane >> 2, tq = lane & 3;

    if (t < 128) sLinv[t] = 1.0f / g_rowsum[(size_t)z * SEQ + m0 + t];

    float acc[2][4][4];
    #pragma unroll
    for (int i = 0; i < 2; i++)
        #pragma unroll
        for (int j = 0; j < 4; j++)
            #pragma unroll
            for (int q = 0; q < 4; q++) acc[i][j][q] = 0.0f;

    auto issue = [&](int ch, int buf) {
        uint32_t fa = sb + CO_F + buf * CTX_F;
        #pragma unroll
        for (int j = 0; j < 4; j++) {
            int idx = j * 256 + t;
            int r = idx >> 3, cb = (idx & 7) << 4;
            CP16(fa + r * 144 + cb, (const char*)(A + (size_t)r * SEQ + ch * 32) + cb);
        }
        uint32_t va = sb + CO_V + buf * (2 * CTX_V);
        int r = t >> 3, cb = (t & 7) << 4;
        CP16(va + r * 144 + cb,          (const char*)(Vh + (size_t)(ch * 32 + r) * D_MODEL) + cb);
        CP16(va + CTX_V + r * 144 + cb,  (const char*)(Vl + (size_t)(ch * 32 + r) * D_MODEL) + cb);
    };

    auto convert = [&](int ch, int buf) {
        const char* f = sm + CO_F + buf * CTX_F;
        #pragma unroll
        for (int j = 0; j < 4; j++) {
            int idx = j * 256 + t;
            int r = idx >> 3, c4 = idx & 7;
            float4 v = *reinterpret_cast<const float4*>(f + r * 144 + c4 * 16);
            float li = sLinv[r];
            v.x *= li; v.y *= li; v.z *= li; v.w *= li;
            *reinterpret_cast<float4*>(A + (size_t)r * SEQ + ch * 32 + c4 * 4) = v;
            bf16 h0, l0, h1, l1, h2, l2, h3, l3;
            split2(v.x, h0, l0); split2(v.y, h1, l1);
            split2(v.z, h2, l2); split2(v.w, h3, l3);
            char* dh = sm + CO_AH + r * 80 + c4 * 8;
            char* dl = sm + CO_AL + r * 80 + c4 * 8;
            reinterpret_cast<__nv_bfloat162*>(dh)[0] = __halves2bfloat162(h0, h1);
            reinterpret_cast<__nv_bfloat162*>(dh)[1] = __halves2bfloat162(h2, h3);
            reinterpret_cast<__nv_bfloat162*>(dl)[0] = __halves2bfloat162(l0, l1);
            reinterpret_cast<__nv_bfloat162*>(dl)[1] = __halves2bfloat162(l2, l3);
        }
    };

    auto compute = [&](int buf) {
        uint32_t aAh = sb + CO_AH;
        uint32_t aAl = sb + CO_AL;
        uint32_t aVh = sb + CO_V + buf * (2 * CTX_V);
        uint32_t aVl = aVh + CTX_V;

        #pragma unroll
        for (int ks = 0; ks < 2; ks++) {
            uint32_t bh[8], bl[8];
            #pragma unroll
            for (int p = 0; p < 2; p++) {
                int nb = wn * 32 + p * 16;
                uint32_t ad = (uint32_t)((ks * 16 + (lane & 7) + ((lane >> 3) & 1) * 8) * 144 +
                                         nb * 2 + (lane >> 4) * 16);
                LDSM4T(bh[4*p], bh[4*p+1], bh[4*p+2], bh[4*p+3], aVh + ad);
                LDSM4T(bl[4*p], bl[4*p+1], bl[4*p+2], bl[4*p+3], aVl + ad);
            }
            uint32_t af[2][4], au[2];
            #pragma unroll
            for (int mi = 0; mi < 2; mi++) {
                au[mi] = (uint32_t)((wm * 32 + mi * 16 + (lane & 15)) * 80 +
                                    ks * 32 + (lane >> 4) * 16);
                LDSM4(af[mi][0], af[mi][1], af[mi][2], af[mi][3], aAh + au[mi]);
            }
            #pragma unroll
            for (int mi = 0; mi < 2; mi++)
                #pragma unroll
                for (int ni = 0; ni < 4; ni++) {
                    int bi = (ni >> 1) * 4 + (ni & 1) * 2;
                    mma_bf16(acc[mi][ni], af[mi], bh[bi], bh[bi + 1]);
                }
            #pragma unroll
            for (int mi = 0; mi < 2; mi++)
                #pragma unroll
                for (int ni = 0; ni < 4; ni++) {
                    int bi = (ni >> 1) * 4 + (ni & 1) * 2;
                    mma_bf16(acc[mi][ni], af[mi], bl[bi], bl[bi + 1]);
                }
            #pragma unroll
            for (int mi = 0; mi < 2; mi++)
                LDSM4(af[mi][0], af[mi][1], af[mi][2], af[mi][3], aAl + au[mi]);
            #pragma unroll
            for (int mi = 0; mi < 2; mi++)
                #pragma unroll
                for (int ni = 0; ni < 4; ni++) {
                    int bi = (ni >> 1) * 4 + (ni & 1) * 2;
                    mma_bf16(acc[mi][ni], af[mi], bh[bi], bh[bi + 1]);
                }
        }
    };

    issue(0, 0);
    CP_COMMIT();
    const int NCH = SEQ / 32;
    for (int ch = 0; ch < NCH; ch++) {
        int buf = ch & 1;
        if (ch + 1 < NCH) { issue(ch + 1, buf ^ 1); CP_COMMIT(); CP_WAIT1(); }
        else              { CP_WAIT0(); }
        __syncthreads();
        convert(ch, buf);
        __syncthreads();
        compute(buf);
        __syncthreads();
    }

    bf16* Ch = g_ctxhi + vb + (size_t)m0 * D_MODEL;
    bf16* Cl = g_ctxlo + vb + (size_t)m0 * D_MODEL;
    #pragma unroll
    for (int mi = 0; mi < 2; mi++) {
        int r0 = wm * 32 + mi * 16 + g;
        #pragma unroll
        for (int ni = 0; ni < 4; ni++) {
            int n = wn * 32 + ni * 8 + 2 * tq;
            bf16 h0, l0, h1, l1;
            split2(acc[mi][ni][0], h0, l0); split2(acc[mi][ni][1], h1, l1);
            *reinterpret_cast<__nv_bfloat162*>(&Ch[(size_t)r0 * D_MODEL + n]) = __halves2bfloat162(h0, h1);
            *reinterpret_cast<__nv_bfloat162*>(&Cl[(size_t)r0 * D_MODEL + n]) = __halves2bfloat162(l0, l1);
            split2(acc[mi][ni][2], h0, l0); split2(acc[mi][ni][3], h1, l1);
            *reinterpret_cast<__nv_bfloat162*>(&Ch[(size_t)(r0 + 8) * D_MODEL + n]) = __halves2bfloat162(h0, h1);
            *reinterpret_cast<__nv_bfloat162*>(&Cl[(size_t)(r0 + 8) * D_MODEL + n]) = __halves2bfloat162(l0, l1);
        }
    }
}

// ---------------- conversion / pointwise kernels ----------------
__global__ void k_xsplit(const float* __restrict__ src,
                         bf16* __restrict__ hi, bf16* __restrict__ lo, long long n)
{
    long long i = (long long)blockIdx.x * blockDim.x + threadIdx.x;
    if (i < NROWS_ATTN) g_rowsum[i] = 0.0f;
    if (i < n) { bf16 h, l; split2(src[i], h, l); hi[i] = h; lo[i] = l; }
}

__device__ __forceinline__ void wsplit_body(const float* __restrict__ W,
                                            bf16* __restrict__ Th, bf16* __restrict__ Tl,
                                            int Kd, int Nd)
{
    __shared__ float tile[32][33];
    int n0 = blockIdx.x * 32, k0 = blockIdx.y * 32;
    int tx = threadIdx.x, ty = threadIdx.y;
    #pragma unroll
    for (int i = 0; i < 4; i++)
        tile[ty + 8 * i][tx] = W[(size_t)(k0 + ty + 8 * i) * Nd + n0 + tx];
    __syncthreads();
    #pragma unroll
    for (int i = 0; i < 4; i++) {
        int n = n0 + ty + 8 * i, k = k0 + tx;
        bf16 h, l; split2(tile[tx][ty + 8 * i], h, l);
        Th[(size_t)n * Kd + k] = h;
        Tl[(size_t)n * Kd + k] = l;
    }
}

__global__ void k_wsplit(const float* __restrict__ W,
                         bf16* __restrict__ Th, bf16* __restrict__ Tl, int Kd, int Nd)
{
    wsplit_body(W, Th, Tl, Kd, Nd);
}

__global__ void k_wsplit4(const float* Wq, const float* Wk, const float* Wv, const float* Wo)
{
    const float* W; bf16 *Th, *Tl;
    switch (blockIdx.z) {
        case 0:  W = Wq; Th = g_wqt_hi; Tl = g_wqt_lo; break;
        case 1:  W = Wk; Th = g_wkt_hi; Tl = g_wkt_lo; break;
        case 2:  W = Wv; Th = g_wvt_hi; Tl = g_wvt_lo; break;
        default: W = Wo; Th = g_wot_hi; Tl = g_wot_lo; break;
    }
    wsplit_body(W, Th, Tl, D_MODEL, D_MODEL);
}

__global__ void k_ln(const float* __restrict__ r, const float* __restrict__ y,
                     const float* __restrict__ g, const float* __restrict__ bta,
                     float* __restrict__ outf,
                     bf16* __restrict__ ohi, bf16* __restrict__ olo)
{
    size_t row = blockIdx.x;
    const float* rp = r + row * D_MODEL;
    const float* yp = y + row * D_MODEL;
    int t = threadIdx.x;
    __shared__ float s1[256], s2[256];
    float v[4]; float sum = 0, sq = 0;
    #pragma unroll
    for (int i = 0; i < 4; i++) {
        int c = t + i * 256;
        float xv = rp[c] + yp[c];
        v[i] = xv; sum += xv; sq += xv * xv;
    }
    s1[t] = sum; s2[t] = sq; __syncthreads();
    for (int s = 128; s > 0; s >>= 1) {
        if (t < s) { s1[t] += s1[t + s]; s2[t] += s2[t + s]; }
        __syncthreads();
    }
    float mu  = s1[0] * (1.0f / D_MODEL);
    float var = s2[0] * (1.0f / D_MODEL) - mu * mu;
    float inv = rsqrtf(var + EPS);
    #pragma unroll
    for (int i = 0; i < 4; i++) {
        int c = t + i * 256;
        float o = (v[i] - mu) * inv * g[c] + bta[c];
        if (outf) outf[row * D_MODEL + c] = o;
        if (ohi) { bf16 h, l; split2(o, h, l);
                   ohi[row * D_MODEL + c] = h; olo[row * D_MODEL + c] = l; }
    }
}

// ---------------- host ----------------
static inline void set_smem(const void* f, int bytes) {
    cudaFuncSetAttribute(f, cudaFuncAttributeMaxDynamicSharedMemorySize, bytes);
}

extern "C" void kernel_launch(void* const* d_in, const int* in_sizes, int n_in,
                              void* d_out, int out_size)
{
    const float* x   = (const float*)d_in[0];
    const float* Wq  = (const float*)d_in[1];
    const float* bq  = (const float*)d_in[2];
    const float* Wk  = (const float*)d_in[3];
    const float* bk  = (const float*)d_in[4];
    const float* Wv  = (const float*)d_in[5];
    const float* bv  = (const float*)d_in[6];
    const float* Wo  = (const float*)d_in[7];
    const float* bo  = (const float*)d_in[8];
    const float* g1  = (const float*)d_in[9];
    const float* b1  = (const float*)d_in[10];
    const float* W1  = (const float*)d_in[11];
    const float* bf1 = (const float*)d_in[12];
    const float* W2  = (const float*)d_in[13];
    const float* bf2 = (const float*)d_in[14];
    const float* g2  = (const float*)d_in[15];
    const float* b2  = (const float*)d_in[16];
    float* out = (float*)d_out;

    float *T1, *H, *ATf;
    bf16 *xhi, *xlo, *w1h, *w1l, *w2h, *w2l, *hhi, *hlo;
    cudaGetSymbolAddress((void**)&T1,  g_T1);
    cudaGetSymbolAddress((void**)&H,   g_H);
    cudaGetSymbolAddress((void**)&ATf, g_attn_fallback);
    cudaGetSymbolAddress((void**)&xhi, g_xhi);  cudaGetSymbolAddress((void**)&xlo, g_xlo);
    cudaGetSymbolAddress((void**)&w1h, g_w1t_hi); cudaGetSymbolAddress((void**)&w1l, g_w1t_lo);
    cudaGetSymbolAddress((void**)&w2h, g_w2t_hi); cudaGetSymbolAddress((void**)&w2l, g_w2t_lo);
    cudaGetSymbolAddress((void**)&hhi, g_hhi);  cudaGetSymbolAddress((void**)&hlo, g_hlo);

    float* attn = ((long long)out_size >= OUT_ELEMS + ATTN_ELEMS) ? (out + OUT_ELEMS) : ATf;

    constexpr int SM_NK = 2 * (2 * 128 * 80 + 2 * 128 * 80);   // 81920
    set_smem((const void*)k_qkv,    SM_NK);
    set_smem((const void*)k_scores, SM_NK);
    set_smem((const void*)k_wo,     SM_NK);
    set_smem((const void*)k_ff1,    SM_NK);
    set_smem((const void*)k_ff2,    SM_NK);
    set_smem((const void*)k_ctx,    CTX_SM);

    dim3 tb(32, 8);
    // input split (+ rowsum zero)
    k_xsplit<<<(ROWS * D_MODEL + 255) / 256, 256>>>(x, xhi, xlo, (long long)ROWS * D_MODEL);
    // weight splits
    k_wsplit4<<<dim3(32, 32, 4), tb>>>(Wq, Wk, Wv, Wo);
    // Q/K/V projections
    k_qkv<<<dim3(D_MODEL / 128, ROWS / 128, 3), 128, SM_NK>>>(bq, bk, bv);
    // FF weight splits
    k_wsplit<<<dim3(128, 32), tb>>>(W1, w1h, w1l, D_MODEL, DFF);
    k_wsplit<<<dim3(32, 128), tb>>>(W2, w2h, w2l, DFF, D_MODEL);
    // scores: u = exp(QK^T/8) + row sums
    k_scores<<<dim3(SEQ / 128, SEQ / 128, BATCH * NH), 128, SM_NK>>>(attn);
    // ctx = (u/rowsum) @ V ; also writes normalized attn output
    k_ctx<<<dim3(1, SEQ / 128, BATCH * NH), 256, CTX_SM>>>(attn);
    // attn_out = ctx @ Wo + bo
    k_wo<<<dim3(D_MODEL / 128, ROWS / 128), 128, SM_NK>>>(bo);
    // h = LN(x + attn_out)
    k_ln<<<ROWS, 256>>>(x, T1, g1, b1, H, hhi, hlo);
    // ff = gelu(h @ W1 + bf1)
    k_ff1<<<dim3(DFF / 128, ROWS / 128), 128, SM_NK>>>(bf1);
    // ff2 = ff @ W2 + bf2
    k_ff2<<<dim3(D_MODEL / 128, ROWS / 128), 128, SM_NK>>>(bf2);
    // out = LN(h + ff2)
    k_ln<<<ROWS, 256>>>(H, T1, g2, b2, out, nullptr, nullptr);
}

// round 17
// speedup vs baseline: 1.0575x; 1.0575x over previous
#include <cuda_runtime.h>
#include <cuda_bf16.h>
#include <math.h>
#include <stdint.h>

typedef __nv_bfloat16 bf16;

constexpr int D_MODEL = 1024;
constexpr int SEQ     = 2048;
constexpr int BATCH   = 2;
constexpr int NH      = 16;
constexpr int DK      = 64;
constexpr int DFF     = 4096;
constexpr int ROWS    = BATCH * SEQ;     // 4096
constexpr float EPS   = 1e-5f;
constexpr long long OUT_ELEMS  = (long long)ROWS * D_MODEL;
constexpr long long ATTN_ELEMS = (long long)BATCH * NH * SEQ * SEQ;
constexpr int NROWS_ATTN = BATCH * NH * SEQ;   // 65536

// ---------------- device scratch ----------------
__device__ bf16 g_xhi [ROWS * D_MODEL], g_xlo [ROWS * D_MODEL];
__device__ bf16 g_wqt_hi[D_MODEL * D_MODEL], g_wqt_lo[D_MODEL * D_MODEL];
__device__ bf16 g_wkt_hi[D_MODEL * D_MODEL], g_wkt_lo[D_MODEL * D_MODEL];
__device__ bf16 g_wvt_hi[D_MODEL * D_MODEL], g_wvt_lo[D_MODEL * D_MODEL];
__device__ bf16 g_wot_hi[D_MODEL * D_MODEL], g_wot_lo[D_MODEL * D_MODEL];
__device__ bf16 g_w1t_hi[(long long)D_MODEL * DFF], g_w1t_lo[(long long)D_MODEL * DFF];
__device__ bf16 g_w2t_hi[(long long)D_MODEL * DFF], g_w2t_lo[(long long)D_MODEL * DFF];
__device__ bf16 g_Qhi [ROWS * D_MODEL], g_Qlo [ROWS * D_MODEL];
__device__ bf16 g_Khi [ROWS * D_MODEL], g_Klo [ROWS * D_MODEL];
__device__ bf16 g_Vhi [ROWS * D_MODEL], g_Vlo [ROWS * D_MODEL];
__device__ bf16 g_ctxhi[ROWS * D_MODEL], g_ctxlo[ROWS * D_MODEL];
__device__ bf16 g_hhi [ROWS * D_MODEL], g_hlo [ROWS * D_MODEL];
__device__ bf16 g_ffhi[(long long)ROWS * DFF], g_fflo[(long long)ROWS * DFF];
__device__ float g_T1[ROWS * D_MODEL];
__device__ float g_H [ROWS * D_MODEL];
__device__ float g_rowsum[NROWS_ATTN];
__device__ float g_attn_fallback[ATTN_ELEMS];

// ---------------- PTX helpers ----------------
__device__ __forceinline__ uint32_t smem_u32(const void* p) {
    uint32_t a;
    asm("{ .reg .u64 t; cvta.to.shared.u64 t, %1; cvt.u32.u64 %0, t; }" : "=r"(a) : "l"(p));
    return a;
}
#define CP16(d, s)   asm volatile("cp.async.cg.shared.global [%0], [%1], 16;" :: "r"(d), "l"(s))
#define CP_COMMIT()  asm volatile("cp.async.commit_group;" ::: "memory")
#define CP_WAIT0()   asm volatile("cp.async.wait_group 0;" ::: "memory")
#define CP_WAIT1()   asm volatile("cp.async.wait_group 1;" ::: "memory")

#define LDSM4(r0, r1, r2, r3, a) \
    asm volatile("ldmatrix.sync.aligned.m8n8.x4.shared.b16 {%0,%1,%2,%3}, [%4];" \
                 : "=r"(r0), "=r"(r1), "=r"(r2), "=r"(r3) : "r"(a))
#define LDSM4T(r0, r1, r2, r3, a) \
    asm volatile("ldmatrix.sync.aligned.m8n8.x4.trans.shared.b16 {%0,%1,%2,%3}, [%4];" \
                 : "=r"(r0), "=r"(r1), "=r"(r2), "=r"(r3) : "r"(a))

__device__ __forceinline__ void mma_bf16(float* c, const uint32_t* a, uint32_t b0, uint32_t b1) {
    asm volatile(
        "mma.sync.aligned.m16n8k16.row.col.f32.bf16.bf16.f32 "
        "{%0,%1,%2,%3}, {%4,%5,%6,%7}, {%8,%9}, {%0,%1,%2,%3};"
        : "+f"(c[0]), "+f"(c[1]), "+f"(c[2]), "+f"(c[3])
        : "r"(a[0]), "r"(a[1]), "r"(a[2]), "r"(a[3]), "r"(b0), "r"(b1));
}

__device__ __forceinline__ void split2(float v, bf16& h, bf16& l) {
    h = __float2bfloat16(v);
    l = __float2bfloat16(v - __bfloat162float(h));
}

// ---------------------------------------------------------------------------
// Split-bf16 GEMM via mma.sync (proven R13 core: 256 thr, 64x32 warp tile).
// RS compile-time: RS=true (k_scores) -> exp epilogue + rowsum, streaming
// stores for the huge u-buffer.  RS=false identical to R11/R13.
// ---------------------------------------------------------------------------
template<int BN, bool RS>
__device__ __forceinline__ void mma_gemm(
    const bf16* __restrict__ Ah, const bf16* __restrict__ Al, int lda,
    const bf16* __restrict__ Bh, const bf16* __restrict__ Bl, int ldb,
    int K, int m0, int n0,
    const float* __restrict__ bias, float scale, int act,
    float* __restrict__ Cf, int ldcf,
    bf16* __restrict__ Chi, bf16* __restrict__ Clo, int ldc2,
    float* __restrict__ rowsum)
{
    constexpr int ASZ   = 128 * 80;
    constexpr int BSZ   = BN * 80;
    constexpr int STAGE = 2 * ASZ + 2 * BSZ;
    constexpr int WN_W  = BN / 32;
    constexpr int WM_W  = 8 / WN_W;
    constexpr int WM    = 128 / WM_W;
    constexpr int M_IT  = WM / 16;

    extern __shared__ char sm[];
    const uint32_t sb = smem_u32(sm);

    const int t = threadIdx.x, lane = t & 31, w = t >> 5;
    const int wm = w / WN_W, wn = w % WN_W;

    float acc[M_IT][4][4];
    #pragma unroll
    for (int i = 0; i < M_IT; i++)
        #pragma unroll
        for (int j = 0; j < 4; j++)
            #pragma unroll
            for (int q = 0; q < 4; q++) acc[i][j][q] = 0.0f;

    const int NCH = K / 32;

    auto issue = [&](int ch, int buf) {
        uint32_t s0 = sb + buf * STAGE;
        int k0 = ch * 32;
        #pragma unroll
        for (int i = 0; i < 2; i++) {
            int c = i * 256 + t;
            int r = c >> 2, cb = (c & 3) << 4;
            const char* gh = (const char*)(Ah + (size_t)(m0 + r) * lda + k0) + cb;
            const char* gl = (const char*)(Al + (size_t)(m0 + r) * lda + k0) + cb;
            CP16(s0 + r * 80 + cb, gh);
            CP16(s0 + ASZ + r * 80 + cb, gl);
        }
        #pragma unroll
        for (int i = 0; i < BN * 4 / 256; i++) {
            int c = i * 256 + t;
            int r = c >> 2, cb = (c & 3) << 4;
            const char* gh = (const char*)(Bh + (size_t)(n0 + r) * ldb + k0) + cb;
            const char* gl = (const char*)(Bl + (size_t)(n0 + r) * ldb + k0) + cb;
            CP16(s0 + 2 * ASZ + r * 80 + cb, gh);
            CP16(s0 + 2 * ASZ + BSZ + r * 80 + cb, gl);
        }
    };

    auto compute = [&](int buf) {
        uint32_t aAh = sb + buf * STAGE;
        uint32_t aAl = aAh + ASZ;
        uint32_t aBh = aAl + ASZ;
        uint32_t aBl = aBh + BSZ;

        #pragma unroll
        for (int ks = 0; ks < 2; ks++) {
            uint32_t bh[8], bl[8];
            #pragma unroll
            for (int p = 0; p < 2; p++) {
                int nb = wn * 32 + p * 16;
                uint32_t ad = (uint32_t)((nb + ((lane >> 4) << 3) + (lane & 7)) * 80 +
                                         ks * 32 + ((lane >> 3) & 1) * 16);
                LDSM4(bh[4*p], bh[4*p+1], bh[4*p+2], bh[4*p+3], aBh + ad);
                LDSM4(bl[4*p], bl[4*p+1], bl[4*p+2], bl[4*p+3], aBl + ad);
            }
            uint32_t af[M_IT][4], au[M_IT];
            #pragma unroll
            for (int mi = 0; mi < M_IT; mi++) {
                au[mi] = (uint32_t)((wm * WM + mi * 16 + (lane & 15)) * 80 +
                                    ks * 32 + (lane >> 4) * 16);
                LDSM4(af[mi][0], af[mi][1], af[mi][2], af[mi][3], aAh + au[mi]);
            }
            #pragma unroll
            for (int mi = 0; mi < M_IT; mi++)
                #pragma unroll
                for (int ni = 0; ni < 4; ni++) {
                    int bi = (ni >> 1) * 4 + (ni & 1) * 2;
                    mma_bf16(acc[mi][ni], af[mi], bh[bi], bh[bi + 1]);
                }
            #pragma unroll
            for (int mi = 0; mi < M_IT; mi++)
                #pragma unroll
                for (int ni = 0; ni < 4; ni++) {
                    int bi = (ni >> 1) * 4 + (ni & 1) * 2;
                    mma_bf16(acc[mi][ni], af[mi], bl[bi], bl[bi + 1]);
                }
            #pragma unroll
            for (int mi = 0; mi < M_IT; mi++)
                LDSM4(af[mi][0], af[mi][1], af[mi][2], af[mi][3], aAl + au[mi]);
            #pragma unroll
            for (int mi = 0; mi < M_IT; mi++)
                #pragma unroll
                for (int ni = 0; ni < 4; ni++) {
                    int bi = (ni >> 1) * 4 + (ni & 1) * 2;
                    mma_bf16(acc[mi][ni], af[mi], bh[bi], bh[bi + 1]);
                }
        }
    };

    issue(0, 0);
    CP_COMMIT();
    for (int ch = 0; ch < NCH; ch++) {
        int buf = ch & 1;
        if (ch + 1 < NCH) { issue(ch + 1, buf ^ 1); CP_COMMIT(); CP_WAIT1(); }
        else              { CP_WAIT0(); }
        __syncthreads();
        compute(buf);
        __syncthreads();
    }

    const int g = lane >> 2, tq = lane & 3;
    float* sRed = reinterpret_cast<float*>(sm);     // reuse pipeline smem (RS only)
    #pragma unroll
    for (int mi = 0; mi < M_IT; mi++) {
        int mA = m0 + wm * WM + mi * 16 + g;
        float srow0 = 0.0f, srow1 = 0.0f;
        #pragma unroll
        for (int ni = 0; ni < 4; ni++) {
            int n = n0 + wn * 32 + ni * 8 + 2 * tq;
            float b0v = 0.f, b1v = 0.f;
            if (bias) { b0v = bias[n]; b1v = bias[n + 1]; }
            float* c = acc[mi][ni];
            float v00 = c[0] * scale + b0v, v01 = c[1] * scale + b1v;
            float v10 = c[2] * scale + b0v, v11 = c[3] * scale + b1v;
            if (act) {
                v00 = v00 * normcdff(v00); v01 = v01 * normcdff(v01);
                v10 = v10 * normcdff(v10); v11 = v11 * normcdff(v11);
            }
            if (RS) {
                v00 = __expf(v00); v01 = __expf(v01);
                v10 = __expf(v10); v11 = __expf(v11);
                srow0 += v00 + v01; srow1 += v10 + v11;
            }
            if (Cf) {
                if (RS) {
                    // streaming stores: u-buffer is huge and not re-read soon
                    __stcs(reinterpret_cast<float2*>(&Cf[(size_t)mA * ldcf + n]),
                           make_float2(v00, v01));
                    __stcs(reinterpret_cast<float2*>(&Cf[(size_t)(mA + 8) * ldcf + n]),
                           make_float2(v10, v11));
                } else {
                    *reinterpret_cast<float2*>(&Cf[(size_t)mA * ldcf + n])       = make_float2(v00, v01);
                    *reinterpret_cast<float2*>(&Cf[(size_t)(mA + 8) * ldcf + n]) = make_float2(v10, v11);
                }
            }
            if (Chi) {
                bf16 h0, l0, h1, l1;
                split2(v00, h0, l0); split2(v01, h1, l1);
                *reinterpret_cast<__nv_bfloat162*>(&Chi[(size_t)mA * ldc2 + n]) = __halves2bfloat162(h0, h1);
                *reinterpret_cast<__nv_bfloat162*>(&Clo[(size_t)mA * ldc2 + n]) = __halves2bfloat162(l0, l1);
                split2(v10, h0, l0); split2(v11, h1, l1);
                *reinterpret_cast<__nv_bfloat162*>(&Chi[(size_t)(mA + 8) * ldc2 + n]) = __halves2bfloat162(h0, h1);
                *reinterpret_cast<__nv_bfloat162*>(&Clo[(size_t)(mA + 8) * ldc2 + n]) = __halves2bfloat162(l0, l1);
            }
        }
        if (RS) {
            #pragma unroll
            for (int s = 1; s <= 2; s <<= 1) {
                srow0 += __shfl_xor_sync(~0u, srow0, s);
                srow1 += __shfl_xor_sync(~0u, srow1, s);
            }
            if (tq == 0) {
                int r0 = wm * WM + mi * 16 + g;
                sRed[r0 * WN_W + wn] = srow0;
                sRed[(r0 + 8) * WN_W + wn] = srow1;
            }
        }
    }
    if (RS) {
        __syncthreads();
        if (t < 128) {
            float s = 0.0f;
            #pragma unroll
            for (int j = 0; j < WN_W; j++) s += sRed[t * WN_W + j];
            atomicAdd(&rowsum[m0 + t], s);
        }
    }
}

// ---------------- GEMM wrapper kernels ----------------
__global__ void __launch_bounds__(256)
k_qkv(const float* bq, const float* bk, const float* bv)
{
    int z = blockIdx.z;
    const bf16 *Bh, *Bl; const float* bias; bf16 *Chi, *Clo;
    if (z == 0)      { Bh = g_wqt_hi; Bl = g_wqt_lo; bias = bq; Chi = g_Qhi; Clo = g_Qlo; }
    else if (z == 1) { Bh = g_wkt_hi; Bl = g_wkt_lo; bias = bk; Chi = g_Khi; Clo = g_Klo; }
    else             { Bh = g_wvt_hi; Bl = g_wvt_lo; bias = bv; Chi = g_Vhi; Clo = g_Vlo; }
    mma_gemm<128, false>(g_xhi, g_xlo, D_MODEL, Bh, Bl, D_MODEL, D_MODEL,
                         blockIdx.y * 128, blockIdx.x * 128,
                         bias, 1.0f, 0, nullptr, 0, Chi, Clo, D_MODEL, nullptr);
}

// scores: writes u = exp(QK^T/8) and row sums (softmax-free path)
__global__ void __launch_bounds__(256)
k_scores(float* attn)
{
    int z = blockIdx.z, b = z >> 4, h = z & 15;
    size_t off = (size_t)b * SEQ * D_MODEL + (size_t)h * DK;
    mma_gemm<128, true>(g_Qhi + off, g_Qlo + off, D_MODEL,
                        g_Khi + off, g_Klo + off, D_MODEL, DK,
                        blockIdx.y * 128, blockIdx.x * 128,
                        nullptr, 0.125f, 0,
                        attn + (size_t)z * SEQ * SEQ, SEQ, nullptr, nullptr, 0,
                        g_rowsum + (size_t)z * SEQ);
}

__global__ void __launch_bounds__(256)
k_wo(const float* bo)
{
    mma_gemm<128, false>(g_ctxhi, g_ctxlo, D_MODEL, g_wot_hi, g_wot_lo, D_MODEL, D_MODEL,
                         blockIdx.y * 128, blockIdx.x * 128,
                         bo, 1.0f, 0, g_T1, D_MODEL, nullptr, nullptr, 0, nullptr);
}

__global__ void __launch_bounds__(256)
k_ff1(const float* bf1)
{
    mma_gemm<128, false>(g_hhi, g_hlo, D_MODEL, g_w1t_hi, g_w1t_lo, D_MODEL, D_MODEL,
                         blockIdx.y * 128, blockIdx.x * 128,
                         bf1, 1.0f, 1, nullptr, 0, g_ffhi, g_fflo, DFF, nullptr);
}

__global__ void __launch_bounds__(256)
k_ff2(const float* bf2)
{
    mma_gemm<128, false>(g_ffhi, g_fflo, DFF, g_w2t_hi, g_w2t_lo, DFF, DFF,
                         blockIdx.y * 128, blockIdx.x * 128,
                         bf2, 1.0f, 0, g_T1, D_MODEL, nullptr, nullptr, 0, nullptr);
}

// ---------------------------------------------------------------------------
// ctx = softmax(attn) @ V. Reads unnormalized u = exp(s), multiplies by
// 1/rowsum during the fp32->split-bf16 convert, writes the NORMALIZED fp32
// back to the attn buffer (streaming store), then MMA.  128x64, K=2048.
// ---------------------------------------------------------------------------
constexpr int CTX_F   = 18432;
constexpr int CTX_AB  = 10240;
constexpr int CTX_V   = 4608;
constexpr int CO_F    = 0;
constexpr int CO_AH   = 2 * CTX_F;
constexpr int CO_AL   = CO_AH + CTX_AB;
constexpr int CO_V    = CO_AL + CTX_AB;
constexpr int CO_LI   = CO_V + 4 * CTX_V;
constexpr int CTX_SM  = CO_LI + 512;

__global__ void __launch_bounds__(256)
k_ctx(float* __restrict__ attn_base)
{
    const int z = blockIdx.z, b = z >> 4, h = z & 15;
    const int m0 = blockIdx.y * 128;
    float* A = attn_base + (size_t)z * SEQ * SEQ + (size_t)m0 * SEQ;
    const size_t vb = (size_t)b * SEQ * D_MODEL + (size_t)h * DK;
    const bf16* Vh = g_Vhi + vb;
    const bf16* Vl = g_Vlo + vb;

    extern __shared__ char sm[];
    const uint32_t sb = smem_u32(sm);
    float* sLinv = reinterpret_cast<float*>(sm + CO_LI);

    const int t = threadIdx.x, lane = t & 31, w = t >> 5;
    const int wm = w >> 1, wn = w & 1;
    const int g = lane >> 2, tq = lane & 3;

    if (t < 128) sLinv[t] = 1.0f / g_rowsum[(size_t)z * SEQ + m0 + t];

    float acc[2][4][4];
    #pragma unroll
    for (int i = 0; i < 2; i++)
        #pragma unroll
        for (int j = 0; j < 4; j++)
            #pragma unroll
            for (int q = 0; q < 4; q++) acc[i][j][q] = 0.0f;

    auto issue = [&](int ch, int buf) {
        uint32_t fa = sb + CO_F + buf * CTX_F;
        #pragma unroll
        for (int j = 0; j < 4; j++) {
            int idx = j * 256 + t;
            int r = idx >> 3, cb = (idx & 7) << 4;
            CP16(fa + r * 144 + cb, (const char*)(A + (size_t)r * SEQ + ch * 32) + cb);
        }
        uint32_t va = sb + CO_V + buf * (2 * CTX_V);
        int r = t >> 3, cb = (t & 7) << 4;
        CP16(va + r * 144 + cb,          (const char*)(Vh + (size_t)(ch * 32 + r) * D_MODEL) + cb);
        CP16(va + CTX_V + r * 144 + cb,  (const char*)(Vl + (size_t)(ch * 32 + r) * D_MODEL) + cb);
    };

    auto convert = [&](int ch, int buf) {
        const char* f = sm + CO_F + buf * CTX_F;
        #pragma unroll
        for (int j = 0; j < 4; j++) {
            int idx = j * 256 + t;
            int r = idx >> 3, c4 = idx & 7;
            float4 v = *reinterpret_cast<const float4*>(f + r * 144 + c4 * 16);
            float li = sLinv[r];
            v.x *= li; v.y *= li; v.z *= li; v.w *= li;
            // normalized softmax prob -> attn output (streaming store, never re-read)
            __stcs(reinterpret_cast<float4*>(A + (size_t)r * SEQ + ch * 32 + c4 * 4), v);
            bf16 h0, l0, h1, l1, h2, l2, h3, l3;
            split2(v.x, h0, l0); split2(v.y, h1, l1);
            split2(v.z, h2, l2); split2(v.w, h3, l3);
            char* dh = sm + CO_AH + r * 80 + c4 * 8;
            char* dl = sm + CO_AL + r * 80 + c4 * 8;
            reinterpret_cast<__nv_bfloat162*>(dh)[0] = __halves2bfloat162(h0, h1);
            reinterpret_cast<__nv_bfloat162*>(dh)[1] = __halves2bfloat162(h2, h3);
            reinterpret_cast<__nv_bfloat162*>(dl)[0] = __halves2bfloat162(l0, l1);
            reinterpret_cast<__nv_bfloat162*>(dl)[1] = __halves2bfloat162(l2, l3);
        }
    };

    auto compute = [&](int buf) {
        uint32_t aAh = sb + CO_AH;
        uint32_t aAl = sb + CO_AL;
        uint32_t aVh = sb + CO_V + buf * (2 * CTX_V);
        uint32_t aVl = aVh + CTX_V;

        #pragma unroll
        for (int ks = 0; ks < 2; ks++) {
            uint32_t bh[8], bl[8];
            #pragma unroll
            for (int p = 0; p < 2; p++) {
                int nb = wn * 32 + p * 16;
                uint32_t ad = (uint32_t)((ks * 16 + (lane & 7) + ((lane >> 3) & 1) * 8) * 144 +
                                         nb * 2 + (lane >> 4) * 16);
                LDSM4T(bh[4*p], bh[4*p+1], bh[4*p+2], bh[4*p+3], aVh + ad);
                LDSM4T(bl[4*p], bl[4*p+1], bl[4*p+2], bl[4*p+3], aVl + ad);
            }
            uint32_t af[2][4], au[2];
            #pragma unroll
            for (int mi = 0; mi < 2; mi++) {
                au[mi] = (uint32_t)((wm * 32 + mi * 16 + (lane & 15)) * 80 +
                                    ks * 32 + (lane >> 4) * 16);
                LDSM4(af[mi][0], af[mi][1], af[mi][2], af[mi][3], aAh + au[mi]);
            }
            #pragma unroll
            for (int mi = 0; mi < 2; mi++)
                #pragma unroll
                for (int ni = 0; ni < 4; ni++) {
                    int bi = (ni >> 1) * 4 + (ni & 1) * 2;
                    mma_bf16(acc[mi][ni], af[mi], bh[bi], bh[bi + 1]);
                }
            #pragma unroll
            for (int mi = 0; mi < 2; mi++)
                #pragma unroll
                for (int ni = 0; ni < 4; ni++) {
                    int bi = (ni >> 1) * 4 + (ni & 1) * 2;
                    mma_bf16(acc[mi][ni], af[mi], bl[bi], bl[bi + 1]);
                }
            #pragma unroll
            for (int mi = 0; mi < 2; mi++)
                LDSM4(af[mi][0], af[mi][1], af[mi][2], af[mi][3], aAl + au[mi]);
            #pragma unroll
            for (int mi = 0; mi < 2; mi++)
                #pragma unroll
                for (int ni = 0; ni < 4; ni++) {
                    int bi = (ni >> 1) * 4 + (ni & 1) * 2;
                    mma_bf16(acc[mi][ni], af[mi], bh[bi], bh[bi + 1]);
                }
        }
    };

    issue(0, 0);
    CP_COMMIT();
    const int NCH = SEQ / 32;
    for (int ch = 0; ch < NCH; ch++) {
        int buf = ch & 1;
        if (ch + 1 < NCH) { issue(ch + 1, buf ^ 1); CP_COMMIT(); CP_WAIT1(); }
        else              { CP_WAIT0(); }
        __syncthreads();
        convert(ch, buf);
        __syncthreads();
        compute(buf);
        __syncthreads();
    }

    bf16* Ch = g_ctxhi + vb + (size_t)m0 * D_MODEL;
    bf16* Cl = g_ctxlo + vb + (size_t)m0 * D_MODEL;
    #pragma unroll
    for (int mi = 0; mi < 2; mi++) {
        int r0 = wm * 32 + mi * 16 + g;
        #pragma unroll
        for (int ni = 0; ni < 4; ni++) {
            int n = wn * 32 + ni * 8 + 2 * tq;
            bf16 h0, l0, h1, l1;
            split2(acc[mi][ni][0], h0, l0); split2(acc[mi][ni][1], h1, l1);
            *reinterpret_cast<__nv_bfloat162*>(&Ch[(size_t)r0 * D_MODEL + n]) = __halves2bfloat162(h0, h1);
            *reinterpret_cast<__nv_bfloat162*>(&Cl[(size_t)r0 * D_MODEL + n]) = __halves2bfloat162(l0, l1);
            split2(acc[mi][ni][2], h0, l0); split2(acc[mi][ni][3], h1, l1);
            *reinterpret_cast<__nv_bfloat162*>(&Ch[(size_t)(r0 + 8) * D_MODEL + n]) = __halves2bfloat162(h0, h1);
            *reinterpret_cast<__nv_bfloat162*>(&Cl[(size_t)(r0 + 8) * D_MODEL + n]) = __halves2bfloat162(l0, l1);
        }
    }
}

// ---------------- conversion / pointwise kernels ----------------
__global__ void k_xsplit(const float* __restrict__ src,
                         bf16* __restrict__ hi, bf16* __restrict__ lo, long long n)
{
    long long i = (long long)blockIdx.x * blockDim.x + threadIdx.x;
    if (i < NROWS_ATTN) g_rowsum[i] = 0.0f;
    if (i < n) { bf16 h, l; split2(src[i], h, l); hi[i] = h; lo[i] = l; }
}

__device__ __forceinline__ void wsplit_body(const float* __restrict__ W,
                                            bf16* __restrict__ Th, bf16* __restrict__ Tl,
                                            int Kd, int Nd)
{
    __shared__ float tile[32][33];
    int n0 = blockIdx.x * 32, k0 = blockIdx.y * 32;
    int tx = threadIdx.x, ty = threadIdx.y;
    #pragma unroll
    for (int i = 0; i < 4; i++)
        tile[ty + 8 * i][tx] = W[(size_t)(k0 + ty + 8 * i) * Nd + n0 + tx];
    __syncthreads();
    #pragma unroll
    for (int i = 0; i < 4; i++) {
        int n = n0 + ty + 8 * i, k = k0 + tx;
        bf16 h, l; split2(tile[tx][ty + 8 * i], h, l);
        Th[(size_t)n * Kd + k] = h;
        Tl[(size_t)n * Kd + k] = l;
    }
}

__global__ void k_wsplit(const float* __restrict__ W,
                         bf16* __restrict__ Th, bf16* __restrict__ Tl, int Kd, int Nd)
{
    wsplit_body(W, Th, Tl, Kd, Nd);
}

__global__ void k_wsplit4(const float* Wq, const float* Wk, const float* Wv, const float* Wo)
{
    const float* W; bf16 *Th, *Tl;
    switch (blockIdx.z) {
        case 0:  W = Wq; Th = g_wqt_hi; Tl = g_wqt_lo; break;
        case 1:  W = Wk; Th = g_wkt_hi; Tl = g_wkt_lo; break;
        case 2:  W = Wv; Th = g_wvt_hi; Tl = g_wvt_lo; break;
        default: W = Wo; Th = g_wot_hi; Tl = g_wot_lo; break;
    }
    wsplit_body(W, Th, Tl, D_MODEL, D_MODEL);
}

__global__ void k_ln(const float* __restrict__ r, const float* __restrict__ y,
                     const float* __restrict__ g, const float* __restrict__ bta,
                     float* __restrict__ outf,
                     bf16* __restrict__ ohi, bf16* __restrict__ olo)
{
    size_t row = blockIdx.x;
    const float* rp = r + row * D_MODEL;
    const float* yp = y + row * D_MODEL;
    int t = threadIdx.x;
    __shared__ float s1[256], s2[256];
    float v[4]; float sum = 0, sq = 0;
    #pragma unroll
    for (int i = 0; i < 4; i++) {
        int c = t + i * 256;
        float xv = rp[c] + yp[c];
        v[i] = xv; sum += xv; sq += xv * xv;
    }
    s1[t] = sum; s2[t] = sq; __syncthreads();
    for (int s = 128; s > 0; s >>= 1) {
        if (t < s) { s1[t] += s1[t + s]; s2[t] += s2[t + s]; }
        __syncthreads();
    }
    float mu  = s1[0] * (1.0f / D_MODEL);
    float var = s2[0] * (1.0f / D_MODEL) - mu * mu;
    float inv = rsqrtf(var + EPS);
    #pragma unroll
    for (int i = 0; i < 4; i++) {
        int c = t + i * 256;
        float o = (v[i] - mu) * inv * g[c] + bta[c];
        if (outf) outf[row * D_MODEL + c] = o;
        if (ohi) { bf16 h, l; split2(o, h, l);
                   ohi[row * D_MODEL + c] = h; olo[row * D_MODEL + c] = l; }
    }
}

// ---------------- host ----------------
static inline void set_smem(const void* f, int bytes) {
    cudaFuncSetAttribute(f, cudaFuncAttributeMaxDynamicSharedMemorySize, bytes);
}

extern "C" void kernel_launch(void* const* d_in, const int* in_sizes, int n_in,
                              void* d_out, int out_size)
{
    const float* x   = (const float*)d_in[0];
    const float* Wq  = (const float*)d_in[1];
    const float* bq  = (const float*)d_in[2];
    const float* Wk  = (const float*)d_in[3];
    const float* bk  = (const float*)d_in[4];
    const float* Wv  = (const float*)d_in[5];
    const float* bv  = (const float*)d_in[6];
    const float* Wo  = (const float*)d_in[7];
    const float* bo  = (const float*)d_in[8];
    const float* g1  = (const float*)d_in[9];
    const float* b1  = (const float*)d_in[10];
    const float* W1  = (const float*)d_in[11];
    const float* bf1 = (const float*)d_in[12];
    const float* W2  = (const float*)d_in[13];
    const float* bf2 = (const float*)d_in[14];
    const float* g2  = (const float*)d_in[15];
    const float* b2  = (const float*)d_in[16];
    float* out = (float*)d_out;

    float *T1, *H, *ATf;
    bf16 *xhi, *xlo, *w1h, *w1l, *w2h, *w2l, *hhi, *hlo;
    cudaGetSymbolAddress((void**)&T1,  g_T1);
    cudaGetSymbolAddress((void**)&H,   g_H);
    cudaGetSymbolAddress((void**)&ATf, g_attn_fallback);
    cudaGetSymbolAddress((void**)&xhi, g_xhi);  cudaGetSymbolAddress((void**)&xlo, g_xlo);
    cudaGetSymbolAddress((void**)&w1h, g_w1t_hi); cudaGetSymbolAddress((void**)&w1l, g_w1t_lo);
    cudaGetSymbolAddress((void**)&w2h, g_w2t_hi); cudaGetSymbolAddress((void**)&w2l, g_w2t_lo);
    cudaGetSymbolAddress((void**)&hhi, g_hhi);  cudaGetSymbolAddress((void**)&hlo, g_hlo);

    float* attn = ((long long)out_size >= OUT_ELEMS + ATTN_ELEMS) ? (out + OUT_ELEMS) : ATf;

    constexpr int SM_NK = 2 * (2 * 128 * 80 + 2 * 128 * 80);   // 81920
    set_smem((const void*)k_qkv,    SM_NK);
    set_smem((const void*)k_scores, SM_NK);
    set_smem((const void*)k_wo,     SM_NK);
    set_smem((const void*)k_ff1,    SM_NK);
    set_smem((const void*)k_ff2,    SM_NK);
    set_smem((const void*)k_ctx,    CTX_SM);

    dim3 tb(32, 8);
    // input split (+ rowsum zero)
    k_xsplit<<<(ROWS * D_MODEL + 255) / 256, 256>>>(x, xhi, xlo, (long long)ROWS * D_MODEL);
    // weight splits
    k_wsplit4<<<dim3(32, 32, 4), tb>>>(Wq, Wk, Wv, Wo);
    // Q/K/V projections
    k_qkv<<<dim3(D_MODEL / 128, ROWS / 128, 3), 256, SM_NK>>>(bq, bk, bv);
    // FF weight splits
    k_wsplit<<<dim3(128, 32), tb>>>(W1, w1h, w1l, D_MODEL, DFF);
    k_wsplit<<<dim3(32, 128), tb>>>(W2, w2h, w2l, DFF, D_MODEL);
    // scores: u = exp(QK^T/8) + row sums (no separate softmax kernel)
    k_scores<<<dim3(SEQ / 128, SEQ / 128, BATCH * NH), 256, SM_NK>>>(attn);
    // ctx = (u/rowsum) @ V ; also writes normalized attn output
    k_ctx<<<dim3(1, SEQ / 128, BATCH * NH), 256, CTX_SM>>>(attn);
    // attn_out = ctx @ Wo + bo
    k_wo<<<dim3(D_MODEL / 128, ROWS / 128), 256, SM_NK>>>(bo);
    // h = LN(x + attn_out)
    k_ln<<<ROWS, 256>>>(x, T1, g1, b1, H, hhi, hlo);
    // ff = gelu(h @ W1 + bf1)
    k_ff1<<<dim3(DFF / 128, ROWS / 128), 256, SM_NK>>>(bf1);
    // ff2 = ff @ W2 + bf2
    k_ff2<<<dim3(D_MODEL / 128, ROWS / 128), 256, SM_NK>>>(bf2);
    // out = LN(h + ff2)
    k_ln<<<ROWS, 256>>>(H, T1, g2, b2, out, nullptr, nullptr);
}